// round 8
// baseline (speedup 1.0000x reference)
#include <cuda_runtime.h>
#include <cstdint>

// ---------------------------------------------------------------------------
// QuanvolutionClassifier, phase form:
//   logits[b,c] = bias[c] + sum_px (w[c,px]*R_w) * cos(x[b,px] - phi_w)
// Round 8: cp.async.bulk (UBLKCP) x staging with mbarrier completion (kills
// the LDGSTS issue-rate bottleneck), SAMP=56 / SPLIT=4 -> grid 588 = one
// wave at 4 CTAs/SM, unpadded conflict-free x layout, fused finalize.
// ---------------------------------------------------------------------------

#define THREADS 256
#define WARPS 8
#define SPLIT 4
#define PX_CTA 196
#define NF4 49                         // float4 per x row (196 floats = 784 B)
#define ROWB 784                       // bytes per x row in smem (no pad)
#define SAMP 56                        // samples per CTA
#define MAXB 8192
#define NGRP_MAX 256

#define SW_FLOATS (PX_CTA * 12)        // 2352 floats = 9408 B
#define SX_BYTES (SAMP * ROWB)         // 43904 B
#define SMEM_BYTES (SW_FLOATS * 4 + SX_BYTES)   // 53312

__device__ float g_part[SPLIT][MAXB][10];
__device__ unsigned int g_flag[NGRP_MAX];

typedef unsigned long long u64;

__device__ __forceinline__ u64 pack2(float x, float y) {
    u64 r; asm("mov.b64 %0, {%1, %2};" : "=l"(r) : "f"(x), "f"(y)); return r;
}
__device__ __forceinline__ u64 fma2(u64 a, u64 b, u64 c) {
    u64 d; asm("fma.rn.f32x2 %0, %1, %2, %3;" : "=l"(d) : "l"(a), "l"(b), "l"(c)); return d;
}
__device__ __forceinline__ float2 unpack2(u64 v) {
    float2 f; asm("mov.b64 {%0, %1}, %2;" : "=f"(f.x), "=f"(f.y) : "l"(v)); return f;
}

struct c2f { float x, y; };
__device__ __forceinline__ c2f cmulf(c2f a, c2f b) {
    return { a.x * b.x - a.y * b.y, a.x * b.y + a.y * b.x };
}

// ---------------------------------------------------------------------------
__global__ void __launch_bounds__(THREADS, 4)
quanv_kernel(const float* __restrict__ x,
             const float* __restrict__ params,
             const float* __restrict__ wmat,
             const float* __restrict__ bias,
             float* __restrict__ out,
             int B, int depth) {
    extern __shared__ float smem[];
    float* sW  = smem;                                 // PX_CTA*12
    float* sXf = smem + SW_FLOATS;                     // SAMP rows x 784 B
    float* sP  = smem + SW_FLOATS;                     // partials overlay
    __shared__ float sRP[8];                           // R[4], phi[4]
    __shared__ unsigned int sArriv;
    __shared__ __align__(8) unsigned long long smbar;

    int tid = threadIdx.x;
    int warp = tid >> 5, lane = tid & 31;
    int part = blockIdx.x & (SPLIT - 1);
    int grp  = blockIdx.x >> 2;
    int b0 = grp * SAMP;
    int pxBase = part * PX_CTA;

    uint32_t mbar = (uint32_t)__cvta_generic_to_shared(&smbar);

    // ---- 0. init mbarrier, make visible ----
    if (tid == 0) {
        asm volatile("mbarrier.init.shared.b64 [%0], %1;" :: "r"(mbar), "r"(1u) : "memory");
    }
    __syncthreads();

    // ---- 1. bulk-copy x rows (one 784B row per thread, tid < SAMP) ----
    if (tid == 0) {
        asm volatile("mbarrier.arrive.expect_tx.shared.b64 _, [%0], %1;"
                     :: "r"(mbar), "r"((uint32_t)SX_BYTES) : "memory");
    }
    if (tid < SAMP) {
        int b = b0 + tid; if (b >= B) b = B - 1;
        const float* src = x + (size_t)b * 784 + pxBase;
        uint32_t dst = (uint32_t)__cvta_generic_to_shared(sXf) + (uint32_t)tid * ROWB;
        asm volatile(
            "cp.async.bulk.shared::cluster.global.mbarrier::complete_tx::bytes "
            "[%0], [%1], %2, [%3];"
            :: "r"(dst), "l"(src), "r"((uint32_t)ROWB), "r"(mbar) : "memory");
    }

    // ---- 2. wmat gather -> regs (overlaps bulk copy stream) ----
    float wv[8];
#pragma unroll
    for (int j = 0; j < 8; ++j) {
        int i = tid + j * THREADS;
        if (i < PX_CTA * 10) {
            int px = i / 10, c = i - px * 10;
            int gpx = pxBase + px;
            int r = gpx / 28, cc = gpx - r * 28;
            int wi = (r & 1) * 2 + (cc & 1);
            int k = ((r >> 1) * 14 + (cc >> 1)) * 4 + wi;
            wv[j] = __ldg(&wmat[c * 784 + k]);
        }
    }

    // ---- 3. wires 0..3: SU(2) composition -> (R, phi) ----
    if (tid < 4) {
        int wire = tid;
        c2f a0{1.f, 0.f}, b0c{0.f, 0.f};
        c2f a1{0.f, 0.f}, b1{1.f, 0.f};
        for (int d = 0; d < depth; ++d) {
            float rz1 = __ldg(&params[(d * 4 + wire) * 3 + 0]);
            float ry  = __ldg(&params[(d * 4 + wire) * 3 + 1]);
            float rz2 = __ldg(&params[(d * 4 + wire) * 3 + 2]);
            float c1v, s1v; __sincosf(0.5f * rz1, &s1v, &c1v);
            c2f p1{c1v, -s1v}, p1c{c1v, s1v};
            a0 = cmulf(a0, p1);  a1 = cmulf(a1, p1);
            b0c = cmulf(b0c, p1c); b1 = cmulf(b1, p1c);
            float cy, sy; __sincosf(0.5f * ry, &sy, &cy);
            c2f na0{cy * a0.x - sy * b0c.x, cy * a0.y - sy * b0c.y};
            c2f nb0{sy * a0.x + cy * b0c.x, sy * a0.y + cy * b0c.y};
            c2f na1{cy * a1.x - sy * b1.x, cy * a1.y - sy * b1.y};
            c2f nb1{sy * a1.x + cy * b1.x, sy * a1.y + cy * b1.y};
            a0 = na0; b0c = nb0; a1 = na1; b1 = nb1;
            float cz, sz; __sincosf(0.5f * rz2, &sz, &cz);
            c2f p2{cz, -sz}, p2c{cz, sz};
            a0 = cmulf(a0, p2);  a1 = cmulf(a1, p2);
            b0c = cmulf(b0c, p2c); b1 = cmulf(b1, p2c);
        }
        float al = 2.f * (a0.x * a0.x + a0.y * a0.y) - 1.f;
        float be = 2.f * (a0.x * a1.x + a0.y * a1.y);
        sRP[wire]     = sqrtf(al * al + be * be);
        sRP[4 + wire] = atan2f(be, al);
    }
    __syncthreads();

    // ---- 4. fold weights (w*R) + phi into smem ----
#pragma unroll
    for (int j = 0; j < 8; ++j) {
        int i = tid + j * THREADS;
        if (i < PX_CTA * 10) {
            int px = i / 10, c = i - px * 10;
            int gpx = pxBase + px;
            int r = gpx / 28, cc = gpx - r * 28;
            int wi = (r & 1) * 2 + (cc & 1);
            sW[px * 12 + c] = wv[j] * sRP[wi];
        }
    }
    if (tid < PX_CTA) {
        int gpx = pxBase + tid;
        int r = gpx / 28, cc = gpx - r * 28;
        int wi = (r & 1) * 2 + (cc & 1);
        sW[tid * 12 + 10] = sRP[4 + wi];
        sW[tid * 12 + 11] = 0.f;
    }
    __syncthreads();

    // ---- 5. wait for x bulk copies ----
    {
        uint32_t done;
        asm volatile(
            "{\n\t.reg .pred p;\n\t"
            "mbarrier.try_wait.parity.shared.b64 p, [%1], %2;\n\t"
            "selp.b32 %0, 1, 0, p;\n\t}"
            : "=r"(done) : "r"(mbar), "r"(0u) : "memory");
        while (!done) {
            asm volatile(
                "{\n\t.reg .pred p;\n\t"
                "mbarrier.try_wait.parity.shared.b64 p, [%1], %2;\n\t"
                "selp.b32 %0, 1, 0, p;\n\t}"
                : "=r"(done) : "r"(mbar), "r"(0u) : "memory");
        }
    }

    // ---- 6. compute: accA = samples lane, accB = samples 32+lane (lane<24) ----
    u64 accA[5] = {0ull, 0ull, 0ull, 0ull, 0ull};
    u64 accB[5] = {0ull, 0ull, 0ull, 0ull, 0ull};
    const float4* xrowA = reinterpret_cast<const float4*>(sXf) + lane * NF4;
    const float4* xrowB = reinterpret_cast<const float4*>(sXf) + (lane + 32) * NF4;
    bool hasB = (lane < 24);

#define PROC_PX(pa, pb, pxi)                                                 \
    {                                                                        \
        const ulonglong2* wp =                                               \
            reinterpret_cast<const ulonglong2*>(sW + (pxi) * 12);            \
        ulonglong2 q0 = wp[0], q1 = wp[1], q2 = wp[2];                       \
        float2 ph = unpack2(q2.y);                                           \
        float za = __cosf((pa) - ph.x);                                      \
        float zb = __cosf((pb) - ph.x);                                      \
        u64 zza = pack2(za, za);                                             \
        u64 zzb = pack2(zb, zb);                                             \
        accA[0] = fma2(q0.x, zza, accA[0]);                                  \
        accB[0] = fma2(q0.x, zzb, accB[0]);                                  \
        accA[1] = fma2(q0.y, zza, accA[1]);                                  \
        accB[1] = fma2(q0.y, zzb, accB[1]);                                  \
        accA[2] = fma2(q1.x, zza, accA[2]);                                  \
        accB[2] = fma2(q1.x, zzb, accB[2]);                                  \
        accA[3] = fma2(q1.y, zza, accA[3]);                                  \
        accB[3] = fma2(q1.y, zzb, accB[3]);                                  \
        accA[4] = fma2(q2.x, zza, accA[4]);                                  \
        accB[4] = fma2(q2.x, zzb, accB[4]);                                  \
    }

#pragma unroll
    for (int t = 0; t < 7; ++t) {
        int j = warp + t * 8;
        if (j < NF4) {
            float4 xa = xrowA[j];
            float4 xb = hasB ? xrowB[j] : xa;
            int pxl = j * 4;
            PROC_PX(xa.x, xb.x, pxl + 0);
            PROC_PX(xa.y, xb.y, pxl + 1);
            PROC_PX(xa.z, xb.z, pxl + 2);
            PROC_PX(xa.w, xb.w, pxl + 3);
        }
    }
#undef PROC_PX

    // ---- 7. per-warp partials -> smem (overlay on x, protected by sync) ----
    __syncthreads();
    {
        float2* ppA = reinterpret_cast<float2*>(sP + (warp * SAMP + lane) * 10);
#pragma unroll
        for (int j = 0; j < 5; ++j) ppA[j] = unpack2(accA[j]);
        if (hasB) {
            float2* ppB = reinterpret_cast<float2*>(sP + (warp * SAMP + lane + 32) * 10);
#pragma unroll
            for (int j = 0; j < 5; ++j) ppB[j] = unpack2(accB[j]);
        }
    }
    __syncthreads();

    // ---- 8. reduce 8 warps -> global partial scratch ----
    for (int idx = tid; idx < SAMP * 10; idx += THREADS) {
        int s = idx / 10, c = idx - s * 10;
        float v = 0.f;
#pragma unroll
        for (int w = 0; w < WARPS; ++w) v += sP[(w * SAMP + s) * 10 + c];
        int b = b0 + s;
        if (b < B && b < MAXB) g_part[part][b][c] = v;
    }

    // ---- 9. completion counter: last CTA of group finalizes ----
    __threadfence();
    __syncthreads();
    if (tid == 0) sArriv = atomicAdd(&g_flag[grp], 1u);
    __syncthreads();
    if (sArriv == SPLIT - 1) {
        if (tid < SAMP) {
            int b = b0 + tid;
            if (b < B) {
                float L[10];
#pragma unroll
                for (int c = 0; c < 10; ++c) {
                    float v = __ldg(&bias[c]);
#pragma unroll
                    for (int p = 0; p < SPLIT; ++p) v += __ldcg(&g_part[p][b][c]);
                    L[c] = v;
                }
                float m = L[0];
#pragma unroll
                for (int c = 1; c < 10; ++c) m = fmaxf(m, L[c]);
                float sum = 0.f;
#pragma unroll
                for (int c = 0; c < 10; ++c) sum += __expf(L[c] - m);
                float lse = m + __logf(sum);
#pragma unroll
                for (int c = 0; c < 10; ++c) out[(size_t)b * 10 + c] = L[c] - lse;
            }
        }
        if (tid == 0) g_flag[grp] = 0u;
    }
}

extern "C" void kernel_launch(void* const* d_in, const int* in_sizes, int n_in,
                              void* d_out, int out_size) {
    const float* x      = (const float*)d_in[0];
    const float* params = (const float*)d_in[1];
    const float* wmat   = (const float*)d_in[2];
    const float* bias   = (const float*)d_in[3];
    float* out = (float*)d_out;

    int B = in_sizes[0] / 784;
    int depth = in_sizes[1] / 12;

    cudaFuncSetAttribute(quanv_kernel,
                         cudaFuncAttributeMaxDynamicSharedMemorySize, SMEM_BYTES);

    int ngroups = (B + SAMP - 1) / SAMP;
    quanv_kernel<<<ngroups * SPLIT, THREADS, SMEM_BYTES>>>(
        x, params, wmat, bias, out, B, depth);
}

// round 10
// speedup vs baseline: 1.3483x; 1.3483x over previous
#include <cuda_runtime.h>
#include <cstdint>

// ---------------------------------------------------------------------------
// QuanvolutionClassifier, phase form:
//   logits[b,c] = bias[c] + sum_px (w[c,px]*R_w) * cos(x[b,px] - phi_w)
// Round 10: consolidate. SAMP=56 / SPLIT=4 -> grid 588 = ONE wave at
// 4 CTAs/SM (32 warps/SM). cp.async staging with div-free row-major loop.
// Div-free wmat gather (one px per thread, 10 channels). Fused finalize.
// ---------------------------------------------------------------------------

#define THREADS 256
#define WARPS 8
#define SPLIT 4
#define PX_CTA 196
#define NF4 49                         // float4 per x row (196 floats = 784 B)
#define ROWB 784
#define SAMP 56
#define MAXB 8192
#define NGRP_MAX 256

#define SX_BYTES (SAMP * ROWB)         // 43904 B (x tile first, 1024-aligned)
#define SW_FLOATS (PX_CTA * 12)        // 2352 floats = 9408 B
#define SMEM_BYTES (SX_BYTES + SW_FLOATS * 4)   // 53312

__device__ float g_part[SPLIT][MAXB][10];
__device__ unsigned int g_flag[NGRP_MAX];

typedef unsigned long long u64;

__device__ __forceinline__ u64 pack2(float x, float y) {
    u64 r; asm("mov.b64 %0, {%1, %2};" : "=l"(r) : "f"(x), "f"(y)); return r;
}
__device__ __forceinline__ u64 fma2(u64 a, u64 b, u64 c) {
    u64 d; asm("fma.rn.f32x2 %0, %1, %2, %3;" : "=l"(d) : "l"(a), "l"(b), "l"(c)); return d;
}
__device__ __forceinline__ float2 unpack2(u64 v) {
    float2 f; asm("mov.b64 {%0, %1}, %2;" : "=f"(f.x), "=f"(f.y) : "l"(v)); return f;
}
__device__ __forceinline__ void cp_async16(uint32_t saddr, const void* gaddr) {
    asm volatile("cp.async.cg.shared.global [%0], [%1], 16;" :: "r"(saddr), "l"(gaddr));
}

struct c2f { float x, y; };
__device__ __forceinline__ c2f cmulf(c2f a, c2f b) {
    return { a.x * b.x - a.y * b.y, a.x * b.y + a.y * b.x };
}

// ---------------------------------------------------------------------------
__global__ void __launch_bounds__(THREADS, 4)
quanv_kernel(const float* __restrict__ x,
             const float* __restrict__ params,
             const float* __restrict__ wmat,
             const float* __restrict__ bias,
             float* __restrict__ out,
             int B, int depth) {
    extern __shared__ float smem[];
    float* sXf = smem;                                 // SAMP rows x 784 B
    float* sW  = smem + SX_BYTES / 4;                  // PX_CTA*12
    float* sP  = smem;                                 // partials overlay on x
    __shared__ float sRP[8];                           // R[4], phi[4]
    __shared__ unsigned int sArriv;

    int tid = threadIdx.x;
    int warp = tid >> 5, lane = tid & 31;
    int part = blockIdx.x & (SPLIT - 1);
    int grp  = blockIdx.x >> 2;
    int b0 = grp * SAMP;
    int pxBase = part * PX_CTA;

    uint32_t sxaddr = (uint32_t)__cvta_generic_to_shared(sXf);

    // ---- 1. stage x: row-major, div-free. warp w rows w, w+8, ... ----
    {
        bool has2 = (lane < NF4 - 32);   // lane < 17
#pragma unroll
        for (int t = 0; t < 7; ++t) {
            int s = warp + t * 8;        // s < 56 always (7*8 = 56)
            int b = b0 + s; if (b >= B) b = B - 1;
            const char* src = (const char*)(x + (size_t)b * 784 + pxBase);
            uint32_t dst = sxaddr + (uint32_t)s * ROWB;
            cp_async16(dst + lane * 16u, src + lane * 16);
            if (has2) cp_async16(dst + (lane + 32) * 16u, src + (lane + 32) * 16);
        }
        asm volatile("cp.async.commit_group;");
    }

    // ---- 2. wmat gather: one pixel per thread (tid < 196), 10 channels ----
    float wv[10];
    int kidx = 0, wi = 0;
    if (tid < PX_CTA) {
        int gpx = pxBase + tid;
        int r = gpx / 28, cc = gpx - r * 28;
        wi = (r & 1) * 2 + (cc & 1);
        kidx = ((r >> 1) * 14 + (cc >> 1)) * 4 + wi;
#pragma unroll
        for (int c = 0; c < 10; ++c)
            wv[c] = __ldg(&wmat[c * 784 + kidx]);
    }

    // ---- 3. wires 0..3: SU(2) composition -> (R, phi) ----
    if (tid < 4) {
        int wire = tid;
        c2f a0{1.f, 0.f}, b0c{0.f, 0.f};
        c2f a1{0.f, 0.f}, b1{1.f, 0.f};
        for (int d = 0; d < depth; ++d) {
            float rz1 = __ldg(&params[(d * 4 + wire) * 3 + 0]);
            float ry  = __ldg(&params[(d * 4 + wire) * 3 + 1]);
            float rz2 = __ldg(&params[(d * 4 + wire) * 3 + 2]);
            float c1v, s1v; __sincosf(0.5f * rz1, &s1v, &c1v);
            c2f p1{c1v, -s1v}, p1c{c1v, s1v};
            a0 = cmulf(a0, p1);  a1 = cmulf(a1, p1);
            b0c = cmulf(b0c, p1c); b1 = cmulf(b1, p1c);
            float cy, sy; __sincosf(0.5f * ry, &sy, &cy);
            c2f na0{cy * a0.x - sy * b0c.x, cy * a0.y - sy * b0c.y};
            c2f nb0{sy * a0.x + cy * b0c.x, sy * a0.y + cy * b0c.y};
            c2f na1{cy * a1.x - sy * b1.x, cy * a1.y - sy * b1.y};
            c2f nb1{sy * a1.x + cy * b1.x, sy * a1.y + cy * b1.y};
            a0 = na0; b0c = nb0; a1 = na1; b1 = nb1;
            float cz, sz; __sincosf(0.5f * rz2, &sz, &cz);
            c2f p2{cz, -sz}, p2c{cz, sz};
            a0 = cmulf(a0, p2);  a1 = cmulf(a1, p2);
            b0c = cmulf(b0c, p2c); b1 = cmulf(b1, p2c);
        }
        float al = 2.f * (a0.x * a0.x + a0.y * a0.y) - 1.f;
        float be = 2.f * (a0.x * a1.x + a0.y * a1.y);
        sRP[wire]     = sqrtf(al * al + be * be);
        sRP[4 + wire] = atan2f(be, al);
    }
    __syncthreads();

    // ---- 4. fold weights (w*R) + phi into smem (one px per thread) ----
    if (tid < PX_CTA) {
        float R  = sRP[wi];
        float ph = sRP[4 + wi];
        float* wr = sW + tid * 12;
#pragma unroll
        for (int c = 0; c < 10; ++c) wr[c] = wv[c] * R;
        wr[10] = ph;
        wr[11] = 0.f;
    }
    asm volatile("cp.async.wait_group 0;");
    __syncthreads();

    // ---- 5. compute: accA = sample lane, accB = sample 32+lane (lane<24) ----
    u64 accA[5] = {0ull, 0ull, 0ull, 0ull, 0ull};
    u64 accB[5] = {0ull, 0ull, 0ull, 0ull, 0ull};
    const float4* xrowA = reinterpret_cast<const float4*>(sXf) + lane * NF4;
    const float4* xrowB = reinterpret_cast<const float4*>(sXf) + (lane + 32) * NF4;
    bool hasB = (lane < 24);

#define PROC_PX(pa, pb, pxi)                                                 \
    {                                                                        \
        const ulonglong2* wp =                                               \
            reinterpret_cast<const ulonglong2*>(sW + (pxi) * 12);            \
        ulonglong2 q0 = wp[0], q1 = wp[1], q2 = wp[2];                       \
        float2 ph = unpack2(q2.y);                                           \
        float za = __cosf((pa) - ph.x);                                      \
        float zb = __cosf((pb) - ph.x);                                      \
        u64 zza = pack2(za, za);                                             \
        u64 zzb = pack2(zb, zb);                                             \
        accA[0] = fma2(q0.x, zza, accA[0]);                                  \
        accB[0] = fma2(q0.x, zzb, accB[0]);                                  \
        accA[1] = fma2(q0.y, zza, accA[1]);                                  \
        accB[1] = fma2(q0.y, zzb, accB[1]);                                  \
        accA[2] = fma2(q1.x, zza, accA[2]);                                  \
        accB[2] = fma2(q1.x, zzb, accB[2]);                                  \
        accA[3] = fma2(q1.y, zza, accA[3]);                                  \
        accB[3] = fma2(q1.y, zzb, accB[3]);                                  \
        accA[4] = fma2(q2.x, zza, accA[4]);                                  \
        accB[4] = fma2(q2.x, zzb, accB[4]);                                  \
    }

#pragma unroll
    for (int t = 0; t < 7; ++t) {
        int j = warp + t * 8;
        if (j < NF4) {
            float4 xa = xrowA[j];
            float4 xb = hasB ? xrowB[j] : xa;
            int pxl = j * 4;
            PROC_PX(xa.x, xb.x, pxl + 0);
            PROC_PX(xa.y, xb.y, pxl + 1);
            PROC_PX(xa.z, xb.z, pxl + 2);
            PROC_PX(xa.w, xb.w, pxl + 3);
        }
    }
#undef PROC_PX

    // ---- 6. per-warp partials -> smem (overlay on x, protected by sync) ----
    __syncthreads();
    {
        float2* ppA = reinterpret_cast<float2*>(sP + (warp * SAMP + lane) * 10);
#pragma unroll
        for (int j = 0; j < 5; ++j) ppA[j] = unpack2(accA[j]);
        if (hasB) {
            float2* ppB = reinterpret_cast<float2*>(sP + (warp * SAMP + lane + 32) * 10);
#pragma unroll
            for (int j = 0; j < 5; ++j) ppB[j] = unpack2(accB[j]);
        }
    }
    __syncthreads();

    // ---- 7. reduce 8 warps -> global partial scratch ----
    for (int idx = tid; idx < SAMP * 10; idx += THREADS) {
        int s = idx / 10, c = idx - s * 10;
        float v = 0.f;
#pragma unroll
        for (int w = 0; w < WARPS; ++w) v += sP[(w * SAMP + s) * 10 + c];
        int b = b0 + s;
        if (b < B && b < MAXB) g_part[part][b][c] = v;
    }

    // ---- 8. completion counter: last CTA of group finalizes ----
    __threadfence();
    __syncthreads();
    if (tid == 0) sArriv = atomicAdd(&g_flag[grp], 1u);
    __syncthreads();
    if (sArriv == SPLIT - 1) {
        if (tid < SAMP) {
            int b = b0 + tid;
            if (b < B) {
                float L[10];
#pragma unroll
                for (int c = 0; c < 10; ++c) {
                    float v = __ldg(&bias[c]);
#pragma unroll
                    for (int p = 0; p < SPLIT; ++p) v += __ldcg(&g_part[p][b][c]);
                    L[c] = v;
                }
                float m = L[0];
#pragma unroll
                for (int c = 1; c < 10; ++c) m = fmaxf(m, L[c]);
                float sum = 0.f;
#pragma unroll
                for (int c = 0; c < 10; ++c) sum += __expf(L[c] - m);
                float lse = m + __logf(sum);
#pragma unroll
                for (int c = 0; c < 10; ++c) out[(size_t)b * 10 + c] = L[c] - lse;
            }
        }
        if (tid == 0) g_flag[grp] = 0u;
    }
}

extern "C" void kernel_launch(void* const* d_in, const int* in_sizes, int n_in,
                              void* d_out, int out_size) {
    const float* x      = (const float*)d_in[0];
    const float* params = (const float*)d_in[1];
    const float* wmat   = (const float*)d_in[2];
    const float* bias   = (const float*)d_in[3];
    float* out = (float*)d_out;

    int B = in_sizes[0] / 784;
    int depth = in_sizes[1] / 12;

    cudaFuncSetAttribute(quanv_kernel,
                         cudaFuncAttributeMaxDynamicSharedMemorySize, SMEM_BYTES);

    int ngroups = (B + SAMP - 1) / SAMP;
    quanv_kernel<<<ngroups * SPLIT, THREADS, SMEM_BYTES>>>(
        x, params, wmat, bias, out, B, depth);
}

// round 12
// speedup vs baseline: 1.3636x; 1.0114x over previous
#include <cuda_runtime.h>
#include <cstdint>

// ---------------------------------------------------------------------------
// QuanvolutionClassifier, phase form:
//   logits[b,c] = bias[c] + sum_px (w[c,px]*R_w) * cos(x[b,px] - phi_w)
// Round 11: pipelined column-group staging (7 cp.async commit groups, compute
// iteration t waits only for group t) -> staging drain overlaps compute.
// SAMP=56 / SPLIT=4 -> grid 588 = one wave at 4 CTAs/SM. Fused finalize.
// ---------------------------------------------------------------------------

#define THREADS 256
#define WARPS 8
#define SPLIT 4
#define PX_CTA 196
#define NF4 49                         // float4 per x row (196 floats = 784 B)
#define ROWB 784
#define SAMP 56
#define MAXB 8192
#define NGRP_MAX 256

#define SX_BYTES (SAMP * ROWB)         // 43904 B (x tile first, aligned)
#define SW_FLOATS (PX_CTA * 12)        // 2352 floats = 9408 B
#define SMEM_BYTES (SX_BYTES + SW_FLOATS * 4)   // 53312

__device__ float g_part[SPLIT][MAXB][10];
__device__ unsigned int g_flag[NGRP_MAX];

typedef unsigned long long u64;

__device__ __forceinline__ u64 pack2(float x, float y) {
    u64 r; asm("mov.b64 %0, {%1, %2};" : "=l"(r) : "f"(x), "f"(y)); return r;
}
__device__ __forceinline__ u64 fma2(u64 a, u64 b, u64 c) {
    u64 d; asm("fma.rn.f32x2 %0, %1, %2, %3;" : "=l"(d) : "l"(a), "l"(b), "l"(c)); return d;
}
__device__ __forceinline__ float2 unpack2(u64 v) {
    float2 f; asm("mov.b64 {%0, %1}, %2;" : "=f"(f.x), "=f"(f.y) : "l"(v)); return f;
}
__device__ __forceinline__ void cp_async16(uint32_t saddr, const void* gaddr) {
    asm volatile("cp.async.cg.shared.global [%0], [%1], 16;" :: "r"(saddr), "l"(gaddr));
}

struct c2f { float x, y; };
__device__ __forceinline__ c2f cmulf(c2f a, c2f b) {
    return { a.x * b.x - a.y * b.y, a.x * b.y + a.y * b.x };
}

// ---------------------------------------------------------------------------
__global__ void __launch_bounds__(THREADS, 4)
quanv_kernel(const float* __restrict__ x,
             const float* __restrict__ params,
             const float* __restrict__ wmat,
             const float* __restrict__ bias,
             float* __restrict__ out,
             int B, int depth) {
    extern __shared__ float smem[];
    float* sXf = smem;                                 // SAMP rows x 784 B
    float* sW  = smem + SX_BYTES / 4;                  // PX_CTA*12
    float* sP  = smem;                                 // partials overlay on x
    __shared__ float sRP[8];                           // R[4], phi[4]
    __shared__ unsigned int sArriv;

    int tid = threadIdx.x;
    int warp = tid >> 5, lane = tid & 31;
    int part = blockIdx.x & (SPLIT - 1);
    int grp  = blockIdx.x >> 2;
    int b0 = grp * SAMP;
    int pxBase = part * PX_CTA;

    uint32_t sxaddr = (uint32_t)__cvta_generic_to_shared(sXf);

    // ---- 1. stage x in 7 column-group commit groups ----
    // group g (g<6): f4 cols [8g, 8g+8) x 56 rows = 448 f4; thread handles
    // (tid) and (tid+256). group 6: col 48 x 56 rows.
    {
        int i0 = tid;
        int i1 = tid + 256;
        int s0 = i0 >> 3, jj0 = i0 & 7;
        int s1 = i1 >> 3, jj1 = i1 & 7;
        int bb0 = b0 + s0; if (bb0 >= B) bb0 = B - 1;
        int bb1 = b0 + s1; if (bb1 >= B) bb1 = B - 1;
        const char* srow0 = (const char*)(x + (size_t)bb0 * 784 + pxBase);
        const char* srow1 = (const char*)(x + (size_t)bb1 * 784 + pxBase);
        uint32_t drow0 = sxaddr + (uint32_t)s0 * ROWB;
        uint32_t drow1 = sxaddr + (uint32_t)s1 * ROWB;
        bool h1 = (i1 < 448);
#pragma unroll
        for (int g = 0; g < 6; ++g) {
            int j0 = 8 * g + jj0;
            int j1 = 8 * g + jj1;
            cp_async16(drow0 + (uint32_t)j0 * 16u, srow0 + j0 * 16);
            if (h1) cp_async16(drow1 + (uint32_t)j1 * 16u, srow1 + j1 * 16);
            asm volatile("cp.async.commit_group;");
        }
        if (tid < SAMP) {
            int b = b0 + tid; if (b >= B) b = B - 1;
            cp_async16(sxaddr + (uint32_t)tid * ROWB + 48u * 16u,
                       (const char*)(x + (size_t)b * 784 + pxBase) + 48 * 16);
        }
        asm volatile("cp.async.commit_group;");
    }

    // ---- 2. wires 0..3: SU(2) composition -> (R, phi)  (before gather so
    //         wv[] isn't live across this register-heavy block) ----
    if (tid < 4) {
        int wire = tid;
        c2f a0{1.f, 0.f}, b0c{0.f, 0.f};
        c2f a1{0.f, 0.f}, b1{1.f, 0.f};
        for (int d = 0; d < depth; ++d) {
            float rz1 = __ldg(&params[(d * 4 + wire) * 3 + 0]);
            float ry  = __ldg(&params[(d * 4 + wire) * 3 + 1]);
            float rz2 = __ldg(&params[(d * 4 + wire) * 3 + 2]);
            float c1v, s1v; __sincosf(0.5f * rz1, &s1v, &c1v);
            c2f p1{c1v, -s1v}, p1c{c1v, s1v};
            a0 = cmulf(a0, p1);  a1 = cmulf(a1, p1);
            b0c = cmulf(b0c, p1c); b1 = cmulf(b1, p1c);
            float cy, sy; __sincosf(0.5f * ry, &sy, &cy);
            c2f na0{cy * a0.x - sy * b0c.x, cy * a0.y - sy * b0c.y};
            c2f nb0{sy * a0.x + cy * b0c.x, sy * a0.y + cy * b0c.y};
            c2f na1{cy * a1.x - sy * b1.x, cy * a1.y - sy * b1.y};
            c2f nb1{sy * a1.x + cy * b1.x, sy * a1.y + cy * b1.y};
            a0 = na0; b0c = nb0; a1 = na1; b1 = nb1;
            float cz, sz; __sincosf(0.5f * rz2, &sz, &cz);
            c2f p2{cz, -sz}, p2c{cz, sz};
            a0 = cmulf(a0, p2);  a1 = cmulf(a1, p2);
            b0c = cmulf(b0c, p2c); b1 = cmulf(b1, p2c);
        }
        float al = 2.f * (a0.x * a0.x + a0.y * a0.y) - 1.f;
        float be = 2.f * (a0.x * a1.x + a0.y * a1.y);
        sRP[wire]     = sqrtf(al * al + be * be);
        sRP[4 + wire] = atan2f(be, al);
    }

    // ---- 3. wmat gather: one pixel per thread (tid < 196), 10 channels ----
    float wv[10];
    int wi = 0;
    if (tid < PX_CTA) {
        int gpx = pxBase + tid;
        int r = gpx / 28, cc = gpx - r * 28;
        wi = (r & 1) * 2 + (cc & 1);
        int kidx = ((r >> 1) * 14 + (cc >> 1)) * 4 + wi;
#pragma unroll
        for (int c = 0; c < 10; ++c)
            wv[c] = __ldg(&wmat[c * 784 + kidx]);
    }
    __syncthreads();

    // ---- 4. fold weights (w*R) + phi into smem ----
    if (tid < PX_CTA) {
        float R  = sRP[wi];
        float ph = sRP[4 + wi];
        float* wr = sW + tid * 12;
#pragma unroll
        for (int c = 0; c < 10; ++c) wr[c] = wv[c] * R;
        wr[10] = ph;
        wr[11] = 0.f;
    }

    // ---- 5. compute, pipelined against staging groups ----
    u64 accA[5] = {0ull, 0ull, 0ull, 0ull, 0ull};
    u64 accB[5] = {0ull, 0ull, 0ull, 0ull, 0ull};
    const float4* xrowA = reinterpret_cast<const float4*>(sXf) + lane * NF4;
    const float4* xrowB = reinterpret_cast<const float4*>(sXf) + (lane + 32) * NF4;
    bool hasB = (lane < 24);

#define PROC_PX(pa, pb, pxi)                                                 \
    {                                                                        \
        const ulonglong2* wp =                                               \
            reinterpret_cast<const ulonglong2*>(sW + (pxi) * 12);            \
        ulonglong2 q0 = wp[0], q1 = wp[1], q2 = wp[2];                       \
        float2 ph = unpack2(q2.y);                                           \
        float za = __cosf((pa) - ph.x);                                      \
        float zb = __cosf((pb) - ph.x);                                      \
        u64 zza = pack2(za, za);                                             \
        u64 zzb = pack2(zb, zb);                                             \
        accA[0] = fma2(q0.x, zza, accA[0]);                                  \
        accB[0] = fma2(q0.x, zzb, accB[0]);                                  \
        accA[1] = fma2(q0.y, zza, accA[1]);                                  \
        accB[1] = fma2(q0.y, zzb, accB[1]);                                  \
        accA[2] = fma2(q1.x, zza, accA[2]);                                  \
        accB[2] = fma2(q1.x, zzb, accB[2]);                                  \
        accA[3] = fma2(q1.y, zza, accA[3]);                                  \
        accB[3] = fma2(q1.y, zzb, accB[3]);                                  \
        accA[4] = fma2(q2.x, zza, accA[4]);                                  \
        accB[4] = fma2(q2.x, zzb, accB[4]);                                  \
    }

#define STEP(T, NWAIT)                                                       \
    {                                                                        \
        asm volatile("cp.async.wait_group " #NWAIT ";" ::: "memory");        \
        __syncthreads();                                                     \
        int j = warp + 8 * (T);                                              \
        float4 xa = xrowA[j];                                                \
        float4 xb = hasB ? xrowB[j] : xa;                                    \
        int pxl = j * 4;                                                     \
        PROC_PX(xa.x, xb.x, pxl + 0);                                        \
        PROC_PX(xa.y, xb.y, pxl + 1);                                        \
        PROC_PX(xa.z, xb.z, pxl + 2);                                        \
        PROC_PX(xa.w, xb.w, pxl + 3);                                        \
    }

    STEP(0, 6)
    STEP(1, 5)
    STEP(2, 4)
    STEP(3, 3)
    STEP(4, 2)
    STEP(5, 1)
    // t = 6: only quad 48 remains (warp 0)
    asm volatile("cp.async.wait_group 0;" ::: "memory");
    __syncthreads();
    if (warp == 0) {
        float4 xa = xrowA[48];
        float4 xb = hasB ? xrowB[48] : xa;
        PROC_PX(xa.x, xb.x, 192);
        PROC_PX(xa.y, xb.y, 193);
        PROC_PX(xa.z, xb.z, 194);
        PROC_PX(xa.w, xb.w, 195);
    }
#undef STEP
#undef PROC_PX

    // ---- 6. per-warp partials -> smem (overlay on x, protected by sync) ----
    __syncthreads();
    {
        float2* ppA = reinterpret_cast<float2*>(sP + (warp * SAMP + lane) * 10);
#pragma unroll
        for (int j = 0; j < 5; ++j) ppA[j] = unpack2(accA[j]);
        if (hasB) {
            float2* ppB = reinterpret_cast<float2*>(sP + (warp * SAMP + lane + 32) * 10);
#pragma unroll
            for (int j = 0; j < 5; ++j) ppB[j] = unpack2(accB[j]);
        }
    }
    __syncthreads();

    // ---- 7. reduce 8 warps -> global partial scratch ----
    for (int idx = tid; idx < SAMP * 10; idx += THREADS) {
        int s = idx / 10, c = idx - s * 10;
        float v = 0.f;
#pragma unroll
        for (int w = 0; w < WARPS; ++w) v += sP[(w * SAMP + s) * 10 + c];
        int b = b0 + s;
        if (b < B && b < MAXB) g_part[part][b][c] = v;
    }

    // ---- 8. completion counter: last CTA of group finalizes ----
    __threadfence();
    __syncthreads();
    if (tid == 0) sArriv = atomicAdd(&g_flag[grp], 1u);
    __syncthreads();
    if (sArriv == SPLIT - 1) {
        if (tid < SAMP) {
            int b = b0 + tid;
            if (b < B) {
                float L[10];
#pragma unroll
                for (int c = 0; c < 10; ++c) {
                    float v = __ldg(&bias[c]);
#pragma unroll
                    for (int p = 0; p < SPLIT; ++p) v += __ldcg(&g_part[p][b][c]);
                    L[c] = v;
                }
                float m = L[0];
#pragma unroll
                for (int c = 1; c < 10; ++c) m = fmaxf(m, L[c]);
                float sum = 0.f;
#pragma unroll
                for (int c = 0; c < 10; ++c) sum += __expf(L[c] - m);
                float lse = m + __logf(sum);
#pragma unroll
                for (int c = 0; c < 10; ++c) out[(size_t)b * 10 + c] = L[c] - lse;
            }
        }
        if (tid == 0) g_flag[grp] = 0u;
    }
}

extern "C" void kernel_launch(void* const* d_in, const int* in_sizes, int n_in,
                              void* d_out, int out_size) {
    const float* x      = (const float*)d_in[0];
    const float* params = (const float*)d_in[1];
    const float* wmat   = (const float*)d_in[2];
    const float* bias   = (const float*)d_in[3];
    float* out = (float*)d_out;

    int B = in_sizes[0] / 784;
    int depth = in_sizes[1] / 12;

    cudaFuncSetAttribute(quanv_kernel,
                         cudaFuncAttributeMaxDynamicSharedMemorySize, SMEM_BYTES);

    int ngroups = (B + SAMP - 1) / SAMP;
    quanv_kernel<<<ngroups * SPLIT, THREADS, SMEM_BYTES>>>(
        x, params, wmat, bias, out, B, depth);
}